// round 6
// baseline (speedup 1.0000x reference)
#include <cuda_runtime.h>
#include <math.h>

#define N_NODES 5000
#define E_EDGES 160000
#define F_HID   16

typedef unsigned long long ull;

// ---- scratch (device globals: no allocation allowed) ----
__device__ float g_inv[N_NODES];            // deg -> rsqrt(deg)
__device__ float g_h1 [N_NODES * F_HID];    // x @ W1  (red-accumulated)
__device__ float g_a1 [N_NODES * F_HID];    // A_hat @ h1
__device__ float g_hr [N_NODES * F_HID];    // relu(a1 + b1)
__device__ float g_p2 [N_NODES * F_HID];    // A_hat @ hr

// ---------------- f32x2 / red helpers ----------------
__device__ __forceinline__ ull ffma2(ull a, ull b, ull c) {
    ull d;
    asm("fma.rn.f32x2 %0, %1, %2, %3;" : "=l"(d) : "l"(a), "l"(b), "l"(c));
    return d;
}
__device__ __forceinline__ ull fpack(float lo, float hi) {
    ull r;
    asm("mov.b64 %0, {%1, %2};" : "=l"(r) : "f"(lo), "f"(hi));
    return r;
}
__device__ __forceinline__ float2 funpack(ull v) {
    float2 r;
    asm("mov.b64 {%0, %1}, %2;" : "=f"(r.x), "=f"(r.y) : "l"(v));
    return r;
}
__device__ __forceinline__ void red_add_v2(float* p, float a, float b) {
    asm volatile("red.global.add.v2.f32 [%0], {%1, %2};"
                 :: "l"(p), "f"(a), "f"(b) : "memory");
}
__device__ __forceinline__ void red_add_v4(float* p, float a, float b, float c, float d) {
    asm volatile("red.global.add.v4.f32 [%0], {%1, %2, %3, %4};"
                 :: "l"(p), "f"(a), "f"(b), "f"(c), "f"(d) : "memory");
}

// ---------------- init: zero g_h1, g_inv = 1 ----------------
__global__ void k_init() {
    int i = blockIdx.x * blockDim.x + threadIdx.x;
    if (i < N_NODES * F_HID) g_h1[i] = 0.0f;
    if (i < N_NODES) g_inv[i] = 1.0f;   // self loop counts 1
}

__global__ void k_deg_edges(const int* __restrict__ dst) {
    int e = blockIdx.x * blockDim.x + threadIdx.x;
    if (e < E_EDGES) atomicAdd(&g_inv[dst[e]], 1.0f);
}

__global__ void k_rsqrt() {
    int i = blockIdx.x * blockDim.x + threadIdx.x;
    if (i < N_NODES) g_inv[i] = rsqrtf(g_inv[i]);
}

// ---------------- GEMM1: g_h1 += x[N,N] @ W1[N,16] ----------------
// x streamed directly from gmem (zero reuse -> no smem staging).
// Block = 256 threads (8 warps). Warp = 4 rows, 8 lanes per row:
//   lane = ro*8 + lg, row = row0 + warp*4 + ro,
//   lane reads float4s at k = k0 + lg*4 + {0,32,64,96}   (chunk = 128 k)
// -> each warp-LDG covers 4 contiguous 128B lines (perfect coalescing),
//    4 LDG.128 in flight per lane.
// W1 chunk staged to smem as k-pairs (ull), row-padded 17 -> conflict-free.
// f32x2 accumulate; epilogue: 8-lane bfly reduce + red.global.add.v2 per lane.
// Grid = (157 row-blocks, 5 k-splits).
#define G1_KSPLIT 5
#define G1_KR     1000
#define G1_KC     128

__global__ void __launch_bounds__(256) k_gemm1(const float* __restrict__ x,
                                               const float* __restrict__ W1) {
    __shared__ ull sWp[(G1_KC / 2) * 17];    // [64][17] ull = 8704 B
    const int tid  = threadIdx.x;
    const int warp = tid >> 5, lane = tid & 31;
    const int lg = lane & 7, ro = lane >> 3;

    const int row  = blockIdx.x * 32 + warp * 4 + ro;
    const int rowc = (row < N_NODES) ? row : (N_NODES - 1);
    const float* xrow = x + (size_t)rowc * N_NODES;

    const int kbase = blockIdx.y * G1_KR;
    const int kend  = (kbase + G1_KR < N_NODES) ? kbase + G1_KR : N_NODES;

    ull acc[F_HID];
#pragma unroll
    for (int j = 0; j < F_HID; ++j) acc[j] = 0ull;

    for (int k0 = kbase; k0 < kend; k0 += G1_KC) {
        __syncthreads();
        // stage W1 k-pairs: sWp[kp][j] = (W1[k][j], W1[k+1][j]), zero past kend
        for (int idx = tid; idx < (G1_KC / 2) * F_HID; idx += 256) {
            int kp = idx >> 4, j = idx & 15;
            int k = k0 + 2 * kp;
            float w0 = (k     < kend) ? W1[k * F_HID + j]       : 0.0f;
            float w1 = (k + 1 < kend) ? W1[(k + 1) * F_HID + j] : 0.0f;
            sWp[kp * 17 + j] = fpack(w0, w1);
        }
        __syncthreads();

        // 4 float4 loads (independent -> MLP=4), guard at float4 granularity
        float4 v[4];
#pragma unroll
        for (int h = 0; h < 4; ++h) {
            int gk = k0 + lg * 4 + h * 32;
            v[h] = (gk < kend) ? *(const float4*)&xrow[gk]
                               : make_float4(0.f, 0.f, 0.f, 0.f);
        }

#pragma unroll
        for (int h = 0; h < 4; ++h) {
            ulonglong2 xv = *(const ulonglong2*)&v[h];
            const ull* wA = &sWp[(h * 16 + lg * 2) * 17];
            const ull* wB = wA + 17;
#pragma unroll
            for (int j = 0; j < F_HID; ++j) {
                acc[j] = ffma2(xv.x, wA[j], acc[j]);
                acc[j] = ffma2(xv.y, wB[j], acc[j]);
            }
        }
    }

    // reduce across the 8 lanes of each row group (bfly -> all lanes hold sums)
#pragma unroll
    for (int j = 0; j < F_HID; ++j) {
#pragma unroll
        for (int o = 4; o; o >>= 1)
            acc[j] += 0;  // placeholder removed below
    }
    // (64-bit shuffle reduce)
#pragma unroll
    for (int o = 4; o; o >>= 1) {
#pragma unroll
        for (int j = 0; j < F_HID; ++j) {
            float2 a = funpack(acc[j]);
            float2 b;
            b.x = __shfl_xor_sync(0xffffffffu, a.x, o);
            b.y = __shfl_xor_sync(0xffffffffu, a.y, o);
            acc[j] = fpack(a.x + b.x, a.y + b.y);
        }
    }

    if (row < N_NODES) {
        int j0 = lg * 2;
        float2 a = funpack(acc[j0]);
        float2 b = funpack(acc[j0 + 1]);
        red_add_v2(&g_h1[row * F_HID + j0], a.x + a.y, b.x + b.y);
    }
}

// ---------------- 16-wide propagation ----------------
__global__ void k_self1() {
    int t = blockIdx.x * blockDim.x + threadIdx.x;
    if (t >= N_NODES * 4) return;
    int i = t >> 2;
    float iv = g_inv[i], c = iv * iv;
    float4 v = *(const float4*)&g_h1[t * 4];
    v.x *= c; v.y *= c; v.z *= c; v.w *= c;
    *(float4*)&g_a1[t * 4] = v;
}

template <int L>
__global__ void k_edge_agg(const int* __restrict__ src, const int* __restrict__ dst) {
    int e = blockIdx.x * blockDim.x + threadIdx.x;
    if (e >= E_EDGES) return;
    int s = __ldg(src + e), d = __ldg(dst + e);
    const float* feat  = (L == 1) ? g_h1 : g_hr;
    float*       accum = (L == 1) ? g_a1 : g_p2;
    float c = __ldg(&g_inv[s]) * __ldg(&g_inv[d]);
    const float4* f = (const float4*)&feat[s * F_HID];
    float* a = &accum[d * F_HID];
    float4 v0 = f[0], v1 = f[1], v2 = f[2], v3 = f[3];
    red_add_v4(a + 0,  v0.x * c, v0.y * c, v0.z * c, v0.w * c);
    red_add_v4(a + 4,  v1.x * c, v1.y * c, v1.z * c, v1.w * c);
    red_add_v4(a + 8,  v2.x * c, v2.y * c, v2.z * c, v2.w * c);
    red_add_v4(a + 12, v3.x * c, v3.y * c, v3.z * c, v3.w * c);
}

__global__ void k_relu_self2(const float* __restrict__ b1) {
    int t = blockIdx.x * blockDim.x + threadIdx.x;
    if (t >= N_NODES * 4) return;
    int i = t >> 2, q = t & 3;
    float iv = g_inv[i], c = iv * iv;
    float4 b = *(const float4*)&b1[q * 4];
    float4 h = *(const float4*)&g_a1[t * 4];
    h.x = fmaxf(h.x + b.x, 0.f); h.y = fmaxf(h.y + b.y, 0.f);
    h.z = fmaxf(h.z + b.z, 0.f); h.w = fmaxf(h.w + b.w, 0.f);
    *(float4*)&g_hr[t * 4] = h;
    float4 p = make_float4(h.x * c, h.y * c, h.z * c, h.w * c);
    *(float4*)&g_p2[t * 4] = p;
}

// ---------------- GEMM2 + bias + log_softmax, fused ----------------
// Block = 512 threads (16 warps), 8 rows/block, z tile (160 KB) in smem.
// Row-pairs of p2 packed in smem; float4 W2/b2 loads; f32x2 FFMA.
// Softmax: 2 warps per row (half-columns each), combined via smem.
__global__ void __launch_bounds__(512) k_gemm2(const float* __restrict__ W2,
                                               const float* __restrict__ b2,
                                               float* __restrict__ out) {
    extern __shared__ float sZ[];        // [8][N_NODES] = 160000 B
    __shared__ ull   sPp[4 * F_HID];     // packed row pairs of p2
    __shared__ float sRm[16], sRs[16];
    const int tid  = threadIdx.x;
    const int row0 = blockIdx.x * 8;

    if (tid < 4 * F_HID) {
        int pr = tid >> 4, k = tid & 15;
        sPp[tid] = fpack(g_p2[(row0 + 2 * pr) * F_HID + k],
                         g_p2[(row0 + 2 * pr + 1) * F_HID + k]);
    }
    __syncthreads();

    for (int c4 = tid; c4 < N_NODES / 4; c4 += 512) {
        const int c = c4 * 4;
        float4 bv = *(const float4*)&b2[c];
        ull bd0 = fpack(bv.x, bv.x), bd1 = fpack(bv.y, bv.y);
        ull bd2 = fpack(bv.z, bv.z), bd3 = fpack(bv.w, bv.w);
        ull acc[4][4];
#pragma unroll
        for (int pr = 0; pr < 4; ++pr) {
            acc[pr][0] = bd0; acc[pr][1] = bd1; acc[pr][2] = bd2; acc[pr][3] = bd3;
        }
#pragma unroll
        for (int k = 0; k < F_HID; ++k) {
            float4 w = *(const float4*)&W2[k * N_NODES + c];
            ull w0 = fpack(w.x, w.x), w1 = fpack(w.y, w.y);
            ull w2 = fpack(w.z, w.z), w3 = fpack(w.w, w.w);
#pragma unroll
            for (int pr = 0; pr < 4; ++pr) {
                ull pp = sPp[pr * F_HID + k];   // broadcast LDS.64
                acc[pr][0] = ffma2(pp, w0, acc[pr][0]);
                acc[pr][1] = ffma2(pp, w1, acc[pr][1]);
                acc[pr][2] = ffma2(pp, w2, acc[pr][2]);
                acc[pr][3] = ffma2(pp, w3, acc[pr][3]);
            }
        }
#pragma unroll
        for (int pr = 0; pr < 4; ++pr) {
            float2 a0 = funpack(acc[pr][0]), a1 = funpack(acc[pr][1]);
            float2 a2 = funpack(acc[pr][2]), a3 = funpack(acc[pr][3]);
            *(float4*)&sZ[(2 * pr)     * N_NODES + c] = make_float4(a0.x, a1.x, a2.x, a3.x);
            *(float4*)&sZ[(2 * pr + 1) * N_NODES + c] = make_float4(a0.y, a1.y, a2.y, a3.y);
        }
    }
    __syncthreads();

    const int warp = tid >> 5, lane = tid & 31;
    const int rrow = warp & 7, half = warp >> 3;
    const int f4beg = half * (N_NODES / 8), f4end = f4beg + (N_NODES / 8);  // 625 each
    const float4* z4 = (const float4*)(sZ + rrow * N_NODES);

    float m = -INFINITY;
    for (int i = f4beg + lane; i < f4end; i += 32) {
        float4 v = z4[i];
        m = fmaxf(m, fmaxf(fmaxf(v.x, v.y), fmaxf(v.z, v.w)));
    }
#pragma unroll
    for (int o = 16; o; o >>= 1) m = fmaxf(m, __shfl_xor_sync(0xffffffffu, m, o));
    if (lane == 0) sRm[warp] = m;
    __syncthreads();
    m = fmaxf(sRm[rrow], sRm[rrow + 8]);

    float s = 0.0f;
    for (int i = f4beg + lane; i < f4end; i += 32) {
        float4 v = z4[i];
        s += __expf(v.x - m) + __expf(v.y - m) + __expf(v.z - m) + __expf(v.w - m);
    }
#pragma unroll
    for (int o = 16; o; o >>= 1) s += __shfl_xor_sync(0xffffffffu, s, o);
    if (lane == 0) sRs[warp] = s;
    __syncthreads();
    s = sRs[rrow] + sRs[rrow + 8];

    float lse = m + logf(s);
    float4* orow = (float4*)(out + (size_t)(row0 + rrow) * N_NODES);
    for (int i = f4beg + lane; i < f4end; i += 32) {
        float4 v = z4[i];
        orow[i] = make_float4(v.x - lse, v.y - lse, v.z - lse, v.w - lse);
    }
}

// ---------------- launch ----------------
extern "C" void kernel_launch(void* const* d_in, const int* in_sizes, int n_in,
                              void* d_out, int out_size) {
    const float* x   = (const float*)d_in[0];
    const int*   src = (const int*)  d_in[1];
    const int*   dst = (const int*)  d_in[2];
    const float* W1  = (const float*)d_in[3];
    const float* b1  = (const float*)d_in[4];
    const float* W2  = (const float*)d_in[5];
    const float* b2  = (const float*)d_in[6];
    float* out = (float*)d_out;

    const int smem2 = 8 * N_NODES * (int)sizeof(float);  // 160 KB
    cudaFuncSetAttribute(k_gemm2, cudaFuncAttributeMaxDynamicSharedMemorySize, smem2);

    k_init     <<<(N_NODES * F_HID + 255) / 256, 256>>>();
    k_deg_edges<<<(E_EDGES + 255) / 256, 256>>>(dst);
    k_rsqrt    <<<(N_NODES + 255) / 256, 256>>>();

    dim3 g1((N_NODES + 31) / 32, G1_KSPLIT);   // (157, 5)
    k_gemm1<<<g1, 256>>>(x, W1);

    k_self1<<<(N_NODES * 4 + 255) / 256, 256>>>();
    k_edge_agg<1><<<(E_EDGES + 255) / 256, 256>>>(src, dst);

    k_relu_self2<<<(N_NODES * 4 + 255) / 256, 256>>>(b1);
    k_edge_agg<2><<<(E_EDGES + 255) / 256, 256>>>(src, dst);

    k_gemm2<<<N_NODES / 8, 512, smem2>>>(W2, b2, out);
}

// round 7
// speedup vs baseline: 1.0100x; 1.0100x over previous
#include <cuda_runtime.h>
#include <math.h>

#define N_NODES 5000
#define E_EDGES 160000
#define F_HID   16

typedef unsigned long long ull;

// ---- scratch (device globals: no allocation allowed) ----
__device__ float g_inv[N_NODES];            // deg -> rsqrt(deg)
__device__ float g_h1 [N_NODES * F_HID];    // x @ W1  (red-accumulated)
__device__ float g_a1 [N_NODES * F_HID];    // A_hat @ h1
__device__ float g_hr [N_NODES * F_HID];    // relu(a1 + b1)
__device__ float g_p2 [N_NODES * F_HID];    // A_hat @ hr

// ---------------- f32x2 / red helpers ----------------
__device__ __forceinline__ ull ffma2(ull a, ull b, ull c) {
    ull d;
    asm("fma.rn.f32x2 %0, %1, %2, %3;" : "=l"(d) : "l"(a), "l"(b), "l"(c));
    return d;
}
__device__ __forceinline__ ull fpack(float lo, float hi) {
    ull r;
    asm("mov.b64 %0, {%1, %2};" : "=l"(r) : "f"(lo), "f"(hi));
    return r;
}
__device__ __forceinline__ float2 funpack(ull v) {
    float2 r;
    asm("mov.b64 {%0, %1}, %2;" : "=f"(r.x), "=f"(r.y) : "l"(v));
    return r;
}
__device__ __forceinline__ void red_add_v2(float* p, float a, float b) {
    asm volatile("red.global.add.v2.f32 [%0], {%1, %2};"
                 :: "l"(p), "f"(a), "f"(b) : "memory");
}
__device__ __forceinline__ void red_add_v4(float* p, float a, float b, float c, float d) {
    asm volatile("red.global.add.v4.f32 [%0], {%1, %2, %3, %4};"
                 :: "l"(p), "f"(a), "f"(b), "f"(c), "f"(d) : "memory");
}

// ---------------- init: zero g_h1, g_inv = 1 ----------------
__global__ void k_init() {
    int i = blockIdx.x * blockDim.x + threadIdx.x;
    if (i < N_NODES * F_HID) g_h1[i] = 0.0f;
    if (i < N_NODES) g_inv[i] = 1.0f;   // self loop counts 1
}

__global__ void k_deg_edges(const int* __restrict__ dst) {
    int e = blockIdx.x * blockDim.x + threadIdx.x;
    if (e < E_EDGES) atomicAdd(&g_inv[dst[e]], 1.0f);
}

__global__ void k_rsqrt() {
    int i = blockIdx.x * blockDim.x + threadIdx.x;
    if (i < N_NODES) g_inv[i] = rsqrtf(g_inv[i]);
}

// ---------------- GEMM1: g_h1 += x[N,N] @ W1[N,16] ----------------
// x streamed directly from gmem (zero reuse -> no smem staging).
// Block = 256 threads (8 warps). Warp = 4 rows, 8 lanes per row:
//   lane = ro*8 + lg, row = row0 + warp*4 + ro,
//   lane reads float4s at k = k0 + lg*4 + {0,32,64,96}   (chunk = 128 k)
// -> each warp-LDG covers 4 contiguous 128B lines (perfect coalescing),
//    4 LDG.128 in flight per lane.
// W1 chunk staged to smem as k-pairs (ull), row-padded 17 -> conflict-free.
// f32x2 accumulate; epilogue: 8-lane bfly reduce + red.global.add.v2 per lane.
// Grid = (157 row-blocks, 5 k-splits).
#define G1_KSPLIT 5
#define G1_KR     1000
#define G1_KC     128

__global__ void __launch_bounds__(256) k_gemm1(const float* __restrict__ x,
                                               const float* __restrict__ W1) {
    __shared__ ull sWp[(G1_KC / 2) * 17];    // [64][17] ull = 8704 B
    const int tid  = threadIdx.x;
    const int warp = tid >> 5, lane = tid & 31;
    const int lg = lane & 7, ro = lane >> 3;

    const int row  = blockIdx.x * 32 + warp * 4 + ro;
    const int rowc = (row < N_NODES) ? row : (N_NODES - 1);
    const float* xrow = x + (size_t)rowc * N_NODES;

    const int kbase = blockIdx.y * G1_KR;
    const int kend  = (kbase + G1_KR < N_NODES) ? kbase + G1_KR : N_NODES;

    ull acc[F_HID];
#pragma unroll
    for (int j = 0; j < F_HID; ++j) acc[j] = 0ull;

    for (int k0 = kbase; k0 < kend; k0 += G1_KC) {
        __syncthreads();
        // stage W1 k-pairs: sWp[kp][j] = (W1[k][j], W1[k+1][j]), zero past kend
        for (int idx = tid; idx < (G1_KC / 2) * F_HID; idx += 256) {
            int kp = idx >> 4, j = idx & 15;
            int k = k0 + 2 * kp;
            float w0 = (k     < kend) ? W1[k * F_HID + j]       : 0.0f;
            float w1 = (k + 1 < kend) ? W1[(k + 1) * F_HID + j] : 0.0f;
            sWp[kp * 17 + j] = fpack(w0, w1);
        }
        __syncthreads();

        // 4 float4 loads (independent -> MLP=4), guard at float4 granularity
        float4 v[4];
#pragma unroll
        for (int h = 0; h < 4; ++h) {
            int gk = k0 + lg * 4 + h * 32;
            v[h] = (gk < kend) ? *(const float4*)&xrow[gk]
                               : make_float4(0.f, 0.f, 0.f, 0.f);
        }

#pragma unroll
        for (int h = 0; h < 4; ++h) {
            ulonglong2 xv = *(const ulonglong2*)&v[h];
            const ull* wA = &sWp[(h * 16 + lg * 2) * 17];
            const ull* wB = wA + 17;
#pragma unroll
            for (int j = 0; j < F_HID; ++j) {
                acc[j] = ffma2(xv.x, wA[j], acc[j]);
                acc[j] = ffma2(xv.y, wB[j], acc[j]);
            }
        }
    }

    // reduce across the 8 lanes of each row group (bfly -> all lanes hold sums)
#pragma unroll
    for (int j = 0; j < F_HID; ++j) {
#pragma unroll
        for (int o = 4; o; o >>= 1)
            acc[j] += 0;  // placeholder removed below
    }
    // (64-bit shuffle reduce)
#pragma unroll
    for (int o = 4; o; o >>= 1) {
#pragma unroll
        for (int j = 0; j < F_HID; ++j) {
            float2 a = funpack(acc[j]);
            float2 b;
            b.x = __shfl_xor_sync(0xffffffffu, a.x, o);
            b.y = __shfl_xor_sync(0xffffffffu, a.y, o);
            acc[j] = fpack(a.x + b.x, a.y + b.y);
        }
    }

    if (row < N_NODES) {
        int j0 = lg * 2;
        float2 a = funpack(acc[j0]);
        float2 b = funpack(acc[j0 + 1]);
        red_add_v2(&g_h1[row * F_HID + j0], a.x + a.y, b.x + b.y);
    }
}

// ---------------- 16-wide propagation ----------------
__global__ void k_self1() {
    int t = blockIdx.x * blockDim.x + threadIdx.x;
    if (t >= N_NODES * 4) return;
    int i = t >> 2;
    float iv = g_inv[i], c = iv * iv;
    float4 v = *(const float4*)&g_h1[t * 4];
    v.x *= c; v.y *= c; v.z *= c; v.w *= c;
    *(float4*)&g_a1[t * 4] = v;
}

template <int L>
__global__ void k_edge_agg(const int* __restrict__ src, const int* __restrict__ dst) {
    int e = blockIdx.x * blockDim.x + threadIdx.x;
    if (e >= E_EDGES) return;
    int s = __ldg(src + e), d = __ldg(dst + e);
    const float* feat  = (L == 1) ? g_h1 : g_hr;
    float*       accum = (L == 1) ? g_a1 : g_p2;
    float c = __ldg(&g_inv[s]) * __ldg(&g_inv[d]);
    const float4* f = (const float4*)&feat[s * F_HID];
    float* a = &accum[d * F_HID];
    float4 v0 = f[0], v1 = f[1], v2 = f[2], v3 = f[3];
    red_add_v4(a + 0,  v0.x * c, v0.y * c, v0.z * c, v0.w * c);
    red_add_v4(a + 4,  v1.x * c, v1.y * c, v1.z * c, v1.w * c);
    red_add_v4(a + 8,  v2.x * c, v2.y * c, v2.z * c, v2.w * c);
    red_add_v4(a + 12, v3.x * c, v3.y * c, v3.z * c, v3.w * c);
}

__global__ void k_relu_self2(const float* __restrict__ b1) {
    int t = blockIdx.x * blockDim.x + threadIdx.x;
    if (t >= N_NODES * 4) return;
    int i = t >> 2, q = t & 3;
    float iv = g_inv[i], c = iv * iv;
    float4 b = *(const float4*)&b1[q * 4];
    float4 h = *(const float4*)&g_a1[t * 4];
    h.x = fmaxf(h.x + b.x, 0.f); h.y = fmaxf(h.y + b.y, 0.f);
    h.z = fmaxf(h.z + b.z, 0.f); h.w = fmaxf(h.w + b.w, 0.f);
    *(float4*)&g_hr[t * 4] = h;
    float4 p = make_float4(h.x * c, h.y * c, h.z * c, h.w * c);
    *(float4*)&g_p2[t * 4] = p;
}

// ---------------- GEMM2 + bias + log_softmax, fused ----------------
// Block = 512 threads (16 warps), 8 rows/block, z tile (160 KB) in smem.
// Row-pairs of p2 packed in smem; float4 W2/b2 loads; f32x2 FFMA.
// Softmax: 2 warps per row (half-columns each), combined via smem.
__global__ void __launch_bounds__(512) k_gemm2(const float* __restrict__ W2,
                                               const float* __restrict__ b2,
                                               float* __restrict__ out) {
    extern __shared__ float sZ[];        // [8][N_NODES] = 160000 B
    __shared__ ull   sPp[4 * F_HID];     // packed row pairs of p2
    __shared__ float sRm[16], sRs[16];
    const int tid  = threadIdx.x;
    const int row0 = blockIdx.x * 8;

    if (tid < 4 * F_HID) {
        int pr = tid >> 4, k = tid & 15;
        sPp[tid] = fpack(g_p2[(row0 + 2 * pr) * F_HID + k],
                         g_p2[(row0 + 2 * pr + 1) * F_HID + k]);
    }
    __syncthreads();

    for (int c4 = tid; c4 < N_NODES / 4; c4 += 512) {
        const int c = c4 * 4;
        float4 bv = *(const float4*)&b2[c];
        ull bd0 = fpack(bv.x, bv.x), bd1 = fpack(bv.y, bv.y);
        ull bd2 = fpack(bv.z, bv.z), bd3 = fpack(bv.w, bv.w);
        ull acc[4][4];
#pragma unroll
        for (int pr = 0; pr < 4; ++pr) {
            acc[pr][0] = bd0; acc[pr][1] = bd1; acc[pr][2] = bd2; acc[pr][3] = bd3;
        }
#pragma unroll
        for (int k = 0; k < F_HID; ++k) {
            float4 w = *(const float4*)&W2[k * N_NODES + c];
            ull w0 = fpack(w.x, w.x), w1 = fpack(w.y, w.y);
            ull w2 = fpack(w.z, w.z), w3 = fpack(w.w, w.w);
#pragma unroll
            for (int pr = 0; pr < 4; ++pr) {
                ull pp = sPp[pr * F_HID + k];   // broadcast LDS.64
                acc[pr][0] = ffma2(pp, w0, acc[pr][0]);
                acc[pr][1] = ffma2(pp, w1, acc[pr][1]);
                acc[pr][2] = ffma2(pp, w2, acc[pr][2]);
                acc[pr][3] = ffma2(pp, w3, acc[pr][3]);
            }
        }
#pragma unroll
        for (int pr = 0; pr < 4; ++pr) {
            float2 a0 = funpack(acc[pr][0]), a1 = funpack(acc[pr][1]);
            float2 a2 = funpack(acc[pr][2]), a3 = funpack(acc[pr][3]);
            *(float4*)&sZ[(2 * pr)     * N_NODES + c] = make_float4(a0.x, a1.x, a2.x, a3.x);
            *(float4*)&sZ[(2 * pr + 1) * N_NODES + c] = make_float4(a0.y, a1.y, a2.y, a3.y);
        }
    }
    __syncthreads();

    const int warp = tid >> 5, lane = tid & 31;
    const int rrow = warp & 7, half = warp >> 3;
    const int f4beg = half * (N_NODES / 8), f4end = f4beg + (N_NODES / 8);  // 625 each
    const float4* z4 = (const float4*)(sZ + rrow * N_NODES);

    float m = -INFINITY;
    for (int i = f4beg + lane; i < f4end; i += 32) {
        float4 v = z4[i];
        m = fmaxf(m, fmaxf(fmaxf(v.x, v.y), fmaxf(v.z, v.w)));
    }
#pragma unroll
    for (int o = 16; o; o >>= 1) m = fmaxf(m, __shfl_xor_sync(0xffffffffu, m, o));
    if (lane == 0) sRm[warp] = m;
    __syncthreads();
    m = fmaxf(sRm[rrow], sRm[rrow + 8]);

    float s = 0.0f;
    for (int i = f4beg + lane; i < f4end; i += 32) {
        float4 v = z4[i];
        s += __expf(v.x - m) + __expf(v.y - m) + __expf(v.z - m) + __expf(v.w - m);
    }
#pragma unroll
    for (int o = 16; o; o >>= 1) s += __shfl_xor_sync(0xffffffffu, s, o);
    if (lane == 0) sRs[warp] = s;
    __syncthreads();
    s = sRs[rrow] + sRs[rrow + 8];

    float lse = m + logf(s);
    float4* orow = (float4*)(out + (size_t)(row0 + rrow) * N_NODES);
    for (int i = f4beg + lane; i < f4end; i += 32) {
        float4 v = z4[i];
        orow[i] = make_float4(v.x - lse, v.y - lse, v.z - lse, v.w - lse);
    }
}

// ---------------- launch ----------------
extern "C" void kernel_launch(void* const* d_in, const int* in_sizes, int n_in,
                              void* d_out, int out_size) {
    const float* x   = (const float*)d_in[0];
    const int*   src = (const int*)  d_in[1];
    const int*   dst = (const int*)  d_in[2];
    const float* W1  = (const float*)d_in[3];
    const float* b1  = (const float*)d_in[4];
    const float* W2  = (const float*)d_in[5];
    const float* b2  = (const float*)d_in[6];
    float* out = (float*)d_out;

    const int smem2 = 8 * N_NODES * (int)sizeof(float);  // 160 KB
    cudaFuncSetAttribute(k_gemm2, cudaFuncAttributeMaxDynamicSharedMemorySize, smem2);

    k_init     <<<(N_NODES * F_HID + 255) / 256, 256>>>();
    k_deg_edges<<<(E_EDGES + 255) / 256, 256>>>(dst);
    k_rsqrt    <<<(N_NODES + 255) / 256, 256>>>();

    dim3 g1((N_NODES + 31) / 32, G1_KSPLIT);   // (157, 5)
    k_gemm1<<<g1, 256>>>(x, W1);

    k_self1<<<(N_NODES * 4 + 255) / 256, 256>>>();
    k_edge_agg<1><<<(E_EDGES + 255) / 256, 256>>>(src, dst);

    k_relu_self2<<<(N_NODES * 4 + 255) / 256, 256>>>(b1);
    k_edge_agg<2><<<(E_EDGES + 255) / 256, 256>>>(src, dst);

    k_gemm2<<<N_NODES / 8, 512, smem2>>>(W2, b2, out);
}

// round 8
// speedup vs baseline: 1.5449x; 1.5296x over previous
#include <cuda_runtime.h>
#include <math.h>

#define N_NODES 5000
#define E_EDGES 160000
#define F_HID   16

typedef unsigned long long ull;

// ---- scratch (device globals: no allocation allowed) ----
__device__ float g_inv[N_NODES];            // deg -> rsqrt(deg)
__device__ float g_h1 [N_NODES * F_HID];    // x @ W1  (red-accumulated over k-splits)
__device__ float g_a1 [N_NODES * F_HID];    // A_hat @ h1
__device__ float g_hr [N_NODES * F_HID];    // relu(a1 + b1)
__device__ float g_p2 [N_NODES * F_HID];    // A_hat @ hr

// ---------------- f32x2 / red / cp.async helpers ----------------
__device__ __forceinline__ ull ffma2(ull a, ull b, ull c) {
    ull d;
    asm("fma.rn.f32x2 %0, %1, %2, %3;" : "=l"(d) : "l"(a), "l"(b), "l"(c));
    return d;
}
__device__ __forceinline__ ull fpack(float lo, float hi) {
    ull r;
    asm("mov.b64 %0, {%1, %2};" : "=l"(r) : "f"(lo), "f"(hi));
    return r;
}
__device__ __forceinline__ float2 funpack(ull v) {
    float2 r;
    asm("mov.b64 {%0, %1}, %2;" : "=f"(r.x), "=f"(r.y) : "l"(v));
    return r;
}
__device__ __forceinline__ void red_add_v4(float* p, float a, float b, float c, float d) {
    asm volatile("red.global.add.v4.f32 [%0], {%1, %2, %3, %4};"
                 :: "l"(p), "f"(a), "f"(b), "f"(c), "f"(d) : "memory");
}
__device__ __forceinline__ void cp_async16(unsigned dst, const void* src, int src_bytes) {
    asm volatile("cp.async.cg.shared.global [%0], [%1], 16, %2;"
                 :: "r"(dst), "l"(src), "r"(src_bytes) : "memory");
}
__device__ __forceinline__ void cp_commit() {
    asm volatile("cp.async.commit_group;" ::: "memory");
}
template <int N>
__device__ __forceinline__ void cp_wait() {
    asm volatile("cp.async.wait_group %0;" :: "n"(N) : "memory");
}

// ---------------- init: zero g_h1, g_inv = 1 ----------------
__global__ void k_init() {
    int i = blockIdx.x * blockDim.x + threadIdx.x;
    if (i < N_NODES * F_HID) g_h1[i] = 0.0f;
    if (i < N_NODES) g_inv[i] = 1.0f;   // self loop counts 1
}

__global__ void k_deg_edges(const int* __restrict__ dst) {
    int e = blockIdx.x * blockDim.x + threadIdx.x;
    if (e < E_EDGES) atomicAdd(&g_inv[dst[e]], 1.0f);
}

__global__ void k_rsqrt() {
    int i = blockIdx.x * blockDim.x + threadIdx.x;
    if (i < N_NODES) g_inv[i] = rsqrtf(g_inv[i]);
}

// ---------------- GEMM1: g_h1 += x[N,N] @ W1[N,16] ----------------
// Block = 256 threads, 1024 rows/block; each thread owns 4 full rows
// (local rows t, t+256, t+512, t+768) -> NO cross-lane reduction.
// Accumulators are j-pairs (f32x2): acc[4 rows][8 jp] = 64 regs.
// Per k: 4 broadcast LDS.128 of W (64B) serve 4 rows x 8 jp = 32 FFMA2
//   -> 2 bytes of LDS per FFMA2 (the R5 version paid 8B -> L1 bound).
// x tile (1024 rows x 16 k, stride 20 words) staged with cp.async,
// double-buffered so staging overlaps compute. k-split grid.y = 53.
#define G1_ROWS 1024
#define G1_KC   16
#define G1_KR   96
#define G1_NCH  (G1_KR / G1_KC)   // 6
#define G1_XSTR 20                // smem row stride (words), 16B-aligned

#define G1_XBUF (G1_ROWS * G1_XSTR)        // floats per x buffer (20480)
#define G1_WBUF (G1_KC * F_HID)            // floats per W buffer (256)
#define G1_SMEM ((2 * G1_XBUF + 2 * G1_WBUF) * 4)  // 165888 B

__global__ void __launch_bounds__(256) k_gemm1(const float* __restrict__ x,
                                               const float* __restrict__ W1) {
    extern __shared__ float smem[];
    const unsigned sbase = (unsigned)__cvta_generic_to_shared(smem);
    const int tid   = threadIdx.x;
    const int row0  = blockIdx.x * G1_ROWS;
    const int kbase = blockIdx.y * G1_KR;
    const int kend  = (kbase + G1_KR < N_NODES) ? kbase + G1_KR : N_NODES;

    // buffer offsets (floats): x0, x1, w0, w1
    const unsigned xoff[2] = { 0u, (unsigned)G1_XBUF };
    const unsigned woff[2] = { (unsigned)(2 * G1_XBUF),
                               (unsigned)(2 * G1_XBUF + G1_WBUF) };

    ull acc[4][8];
#pragma unroll
    for (int r = 0; r < 4; ++r)
#pragma unroll
        for (int j = 0; j < 8; ++j) acc[r][j] = 0ull;

    // ---- async stage of chunk ch into buffer b ----
    auto stage = [&](int ch, int b) {
        const int k0 = kbase + ch * G1_KC;
        // x: 4096 float4s, 16 per thread; lanes -> consecutive (row, c4)
#pragma unroll
        for (int i = 0; i < 16; ++i) {
            int idx  = tid + 256 * i;
            int lrow = idx >> 2, c4 = idx & 3;
            int grow = row0 + lrow; if (grow >= N_NODES) grow = N_NODES - 1;
            int gk   = k0 + c4 * 4;
            int ok   = (gk < kend);
            const float* src = x + (size_t)grow * N_NODES + (ok ? gk : 0);
            unsigned dst = sbase + (xoff[b] + lrow * G1_XSTR + c4 * 4) * 4u;
            cp_async16(dst, src, ok ? 16 : 0);
        }
        // W chunk: 16 rows x 64B = 64 float4s
        if (tid < 64) {
            int k = tid >> 2, c4 = tid & 3;
            int gk = k0 + k;
            int ok = (gk < kend);
            const float* src = W1 + (size_t)(ok ? gk : 0) * F_HID + c4 * 4;
            unsigned dst = sbase + (woff[b] + k * F_HID + c4 * 4) * 4u;
            cp_async16(dst, src, ok ? 16 : 0);
        }
        cp_commit();
    };

    stage(0, 0);

#pragma unroll
    for (int ch = 0; ch < G1_NCH; ++ch) {
        const int b = ch & 1;
        if (ch + 1 < G1_NCH) { stage(ch + 1, b ^ 1); cp_wait<1>(); }
        else                 { cp_wait<0>(); }
        __syncthreads();

        const float* sx = smem + xoff[b];
        const ull*   sw = (const ull*)(smem + woff[b]);

#pragma unroll
        for (int kq = 0; kq < 4; ++kq) {
            float4 xv[4];
#pragma unroll
            for (int rr = 0; rr < 4; ++rr)
                xv[rr] = *(const float4*)&sx[(tid + rr * 256) * G1_XSTR + kq * 4];
#pragma unroll
            for (int e = 0; e < 4; ++e) {
                const int k = kq * 4 + e;
                ulonglong2 w01 = *(const ulonglong2*)&sw[k * 8 + 0];
                ulonglong2 w23 = *(const ulonglong2*)&sw[k * 8 + 2];
                ulonglong2 w45 = *(const ulonglong2*)&sw[k * 8 + 4];
                ulonglong2 w67 = *(const ulonglong2*)&sw[k * 8 + 6];
#pragma unroll
                for (int rr = 0; rr < 4; ++rr) {
                    float xs = (e == 0) ? xv[rr].x : (e == 1) ? xv[rr].y
                             : (e == 2) ? xv[rr].z : xv[rr].w;
                    ull xd = fpack(xs, xs);
                    acc[rr][0] = ffma2(xd, w01.x, acc[rr][0]);
                    acc[rr][1] = ffma2(xd, w01.y, acc[rr][1]);
                    acc[rr][2] = ffma2(xd, w23.x, acc[rr][2]);
                    acc[rr][3] = ffma2(xd, w23.y, acc[rr][3]);
                    acc[rr][4] = ffma2(xd, w45.x, acc[rr][4]);
                    acc[rr][5] = ffma2(xd, w45.y, acc[rr][5]);
                    acc[rr][6] = ffma2(xd, w67.x, acc[rr][6]);
                    acc[rr][7] = ffma2(xd, w67.y, acc[rr][7]);
                }
            }
        }
        __syncthreads();
    }

    // epilogue: each thread owns 4 complete rows -> 4x red.v4 per row
#pragma unroll
    for (int rr = 0; rr < 4; ++rr) {
        int row = row0 + tid + rr * 256;
        if (row < N_NODES) {
            float* o = &g_h1[row * F_HID];
            float2 a0 = funpack(acc[rr][0]), a1 = funpack(acc[rr][1]);
            float2 a2 = funpack(acc[rr][2]), a3 = funpack(acc[rr][3]);
            float2 a4 = funpack(acc[rr][4]), a5 = funpack(acc[rr][5]);
            float2 a6 = funpack(acc[rr][6]), a7 = funpack(acc[rr][7]);
            red_add_v4(o + 0,  a0.x, a0.y, a1.x, a1.y);
            red_add_v4(o + 4,  a2.x, a2.y, a3.x, a3.y);
            red_add_v4(o + 8,  a4.x, a4.y, a5.x, a5.y);
            red_add_v4(o + 12, a6.x, a6.y, a7.x, a7.y);
        }
    }
}

// ---------------- 16-wide propagation (R4 proven versions) ----------------
__global__ void k_self1() {
    int t = blockIdx.x * blockDim.x + threadIdx.x;
    if (t >= N_NODES * 4) return;
    int i = t >> 2;
    float iv = g_inv[i], c = iv * iv;
    float4 v = *(const float4*)&g_h1[t * 4];
    v.x *= c; v.y *= c; v.z *= c; v.w *= c;
    *(float4*)&g_a1[t * 4] = v;
}

template <int L>
__global__ void k_edge_agg(const int* __restrict__ src, const int* __restrict__ dst) {
    int t = blockIdx.x * blockDim.x + threadIdx.x;
    if (t >= E_EDGES * 4) return;
    int e = t >> 2, q = t & 3;
    int s = __ldg(src + e), d = __ldg(dst + e);
    const float* feat  = (L == 1) ? g_h1 : g_hr;
    float*       accum = (L == 1) ? g_a1 : g_p2;
    float c = g_inv[s] * g_inv[d];
    float4 v = *(const float4*)&feat[s * F_HID + q * 4];
    float* a = &accum[d * F_HID + q * 4];
    atomicAdd(a + 0, v.x * c);
    atomicAdd(a + 1, v.y * c);
    atomicAdd(a + 2, v.z * c);
    atomicAdd(a + 3, v.w * c);
}

__global__ void k_relu_self2(const float* __restrict__ b1) {
    int t = blockIdx.x * blockDim.x + threadIdx.x;
    if (t >= N_NODES * 4) return;
    int i = t >> 2, q = t & 3;
    float iv = g_inv[i], c = iv * iv;
    float4 b = *(const float4*)&b1[q * 4];
    float4 h = *(const float4*)&g_a1[t * 4];
    h.x = fmaxf(h.x + b.x, 0.f); h.y = fmaxf(h.y + b.y, 0.f);
    h.z = fmaxf(h.z + b.z, 0.f); h.w = fmaxf(h.w + b.w, 0.f);
    *(float4*)&g_hr[t * 4] = h;
    float4 p = make_float4(h.x * c, h.y * c, h.z * c, h.w * c);
    *(float4*)&g_p2[t * 4] = p;
}

// ---------------- GEMM2 + bias + log_softmax, fused (R4 proven) ----------------
__global__ void __launch_bounds__(256) k_gemm2(const float* __restrict__ W2,
                                               const float* __restrict__ b2,
                                               float* __restrict__ out) {
    extern __shared__ float sZ[];        // [8][N_NODES] = 160000 B
    __shared__ ull sPp[4 * F_HID];       // packed row pairs of p2
    const int tid  = threadIdx.x;
    const int row0 = blockIdx.x * 8;

    if (tid < 4 * F_HID) {
        int pr = tid >> 4, k = tid & 15;
        sPp[tid] = fpack(g_p2[(row0 + 2 * pr) * F_HID + k],
                         g_p2[(row0 + 2 * pr + 1) * F_HID + k]);
    }
    __syncthreads();

    for (int c4 = tid; c4 < N_NODES / 4; c4 += 256) {
        const int c = c4 * 4;
        float4 bv = *(const float4*)&b2[c];
        ull bd0 = fpack(bv.x, bv.x), bd1 = fpack(bv.y, bv.y);
        ull bd2 = fpack(bv.z, bv.z), bd3 = fpack(bv.w, bv.w);
        ull acc[4][4];
#pragma unroll
        for (int pr = 0; pr < 4; ++pr) {
            acc[pr][0] = bd0; acc[pr][1] = bd1; acc[pr][2] = bd2; acc[pr][3] = bd3;
        }
#pragma unroll
        for (int k = 0; k < F_HID; ++k) {
            float4 w = *(const float4*)&W2[k * N_NODES + c];
            ull w0 = fpack(w.x, w.x), w1 = fpack(w.y, w.y);
            ull w2 = fpack(w.z, w.z), w3 = fpack(w.w, w.w);
#pragma unroll
            for (int pr = 0; pr < 4; ++pr) {
                ull pp = sPp[pr * F_HID + k];   // broadcast LDS.64
                acc[pr][0] = ffma2(pp, w0, acc[pr][0]);
                acc[pr][1] = ffma2(pp, w1, acc[pr][1]);
                acc[pr][2] = ffma2(pp, w2, acc[pr][2]);
                acc[pr][3] = ffma2(pp, w3, acc[pr][3]);
            }
        }
#pragma unroll
        for (int pr = 0; pr < 4; ++pr) {
            float2 a0 = funpack(acc[pr][0]), a1 = funpack(acc[pr][1]);
            float2 a2 = funpack(acc[pr][2]), a3 = funpack(acc[pr][3]);
            *(float4*)&sZ[(2 * pr)     * N_NODES + c] = make_float4(a0.x, a1.x, a2.x, a3.x);
            *(float4*)&sZ[(2 * pr + 1) * N_NODES + c] = make_float4(a0.y, a1.y, a2.y, a3.y);
        }
    }
    __syncthreads();

    const int warp = tid >> 5, lane = tid & 31;
    const float4* z4 = (const float4*)(sZ + warp * N_NODES);

    float m = -INFINITY;
    for (int i = lane; i < N_NODES / 4; i += 32) {
        float4 v = z4[i];
        m = fmaxf(m, fmaxf(fmaxf(v.x, v.y), fmaxf(v.z, v.w)));
    }
#pragma unroll
    for (int o = 16; o; o >>= 1) m = fmaxf(m, __shfl_xor_sync(0xffffffffu, m, o));

    float s = 0.0f;
    for (int i = lane; i < N_NODES / 4; i += 32) {
        float4 v = z4[i];
        s += __expf(v.x - m) + __expf(v.y - m) + __expf(v.z - m) + __expf(v.w - m);
    }
#pragma unroll
    for (int o = 16; o; o >>= 1) s += __shfl_xor_sync(0xffffffffu, s, o);

    float lse = m + logf(s);
    float4* orow = (float4*)(out + (size_t)(row0 + warp) * N_NODES);
    for (int i = lane; i < N_NODES / 4; i += 32) {
        float4 v = z4[i];
        orow[i] = make_float4(v.x - lse, v.y - lse, v.z - lse, v.w - lse);
    }
}

// ---------------- launch ----------------
extern "C" void kernel_launch(void* const* d_in, const int* in_sizes, int n_in,
                              void* d_out, int out_size) {
    const float* x   = (const float*)d_in[0];
    const int*   src = (const int*)  d_in[1];
    const int*   dst = (const int*)  d_in[2];
    const float* W1  = (const float*)d_in[3];
    const float* b1  = (const float*)d_in[4];
    const float* W2  = (const float*)d_in[5];
    const float* b2  = (const float*)d_in[6];
    float* out = (float*)d_out;

    const int smem2 = 8 * N_NODES * (int)sizeof(float);  // 160 KB
    cudaFuncSetAttribute(k_gemm2, cudaFuncAttributeMaxDynamicSharedMemorySize, smem2);
    cudaFuncSetAttribute(k_gemm1, cudaFuncAttributeMaxDynamicSharedMemorySize, G1_SMEM);

    k_init     <<<(N_NODES * F_HID + 255) / 256, 256>>>();
    k_deg_edges<<<(E_EDGES + 255) / 256, 256>>>(dst);
    k_rsqrt    <<<(N_NODES + 255) / 256, 256>>>();

    dim3 g1((N_NODES + G1_ROWS - 1) / G1_ROWS,      // 5
            (N_NODES + G1_KR - 1) / G1_KR);         // 53
    k_gemm1<<<g1, 256, G1_SMEM>>>(x, W1);

    k_self1<<<(N_NODES * 4 + 255) / 256, 256>>>();
    k_edge_agg<1><<<(E_EDGES * 4 + 255) / 256, 256>>>(src, dst);

    k_relu_self2<<<(N_NODES * 4 + 255) / 256, 256>>>(b1);
    k_edge_agg<2><<<(E_EDGES * 4 + 255) / 256, 256>>>(src, dst);

    k_gemm2<<<N_NODES / 8, 256, smem2>>>(W2, b2, out);
}

// round 9
// speedup vs baseline: 1.6226x; 1.0503x over previous
#include <cuda_runtime.h>
#include <math.h>

#define N_NODES 5000
#define E_EDGES 160000
#define F_HID   16

typedef unsigned long long ull;

// ---- scratch (device globals: no allocation allowed) ----
__device__ float g_inv[N_NODES];            // deg -> rsqrt(deg)
__device__ float g_h1 [N_NODES * F_HID];    // x @ W1  (red-accumulated over k-splits)
__device__ float g_a1 [N_NODES * F_HID];    // A_hat @ h1
__device__ float g_hr [N_NODES * F_HID];    // relu(a1 + b1)
__device__ float g_p2 [N_NODES * F_HID];    // A_hat @ hr

// ---------------- f32x2 / red / cp.async helpers ----------------
__device__ __forceinline__ ull ffma2(ull a, ull b, ull c) {
    ull d;
    asm("fma.rn.f32x2 %0, %1, %2, %3;" : "=l"(d) : "l"(a), "l"(b), "l"(c));
    return d;
}
__device__ __forceinline__ ull fpack(float lo, float hi) {
    ull r;
    asm("mov.b64 %0, {%1, %2};" : "=l"(r) : "f"(lo), "f"(hi));
    return r;
}
__device__ __forceinline__ float2 funpack(ull v) {
    float2 r;
    asm("mov.b64 {%0, %1}, %2;" : "=f"(r.x), "=f"(r.y) : "l"(v));
    return r;
}
__device__ __forceinline__ void red_add_v4(float* p, float a, float b, float c, float d) {
    asm volatile("red.global.add.v4.f32 [%0], {%1, %2, %3, %4};"
                 :: "l"(p), "f"(a), "f"(b), "f"(c), "f"(d) : "memory");
}
__device__ __forceinline__ void cp_async16(unsigned dst, const void* src, int src_bytes) {
    asm volatile("cp.async.cg.shared.global [%0], [%1], 16, %2;"
                 :: "r"(dst), "l"(src), "r"(src_bytes) : "memory");
}
__device__ __forceinline__ void cp_commit() {
    asm volatile("cp.async.commit_group;" ::: "memory");
}
template <int N>
__device__ __forceinline__ void cp_wait() {
    asm volatile("cp.async.wait_group %0;" :: "n"(N) : "memory");
}

// ---------------- init: zero g_h1, g_inv = 1 ----------------
__global__ void k_init() {
    int i = blockIdx.x * blockDim.x + threadIdx.x;
    if (i < N_NODES * F_HID) g_h1[i] = 0.0f;
    if (i < N_NODES) g_inv[i] = 1.0f;   // self loop counts 1
}

__global__ void k_deg_edges(const int* __restrict__ dst) {
    int e = blockIdx.x * blockDim.x + threadIdx.x;
    if (e < E_EDGES) atomicAdd(&g_inv[dst[e]], 1.0f);
}

__global__ void k_rsqrt() {
    int i = blockIdx.x * blockDim.x + threadIdx.x;
    if (i < N_NODES) g_inv[i] = rsqrtf(g_inv[i]);
}

// ---------------- GEMM1: g_h1 += x[N,N] @ W1[N,16] ----------------
// Block = 512 threads (16 warps), 1024 rows/block; each thread owns 2 full
// rows (t, t+512) -> NO cross-lane reduction. Accumulators are j-pairs
// (f32x2): acc[2][8] = 32 regs. W chunk broadcast via uniform LDS.128.
// x tile (1024 rows x 16 k, stride 20 words) staged with cp.async,
// double-buffered. K-split tuned to a SINGLE wave:
//   KR = 176 (11 chunks of 16), 29 splits x 5 row-groups = 145 blocks <= 148 SM.
#define G1_ROWS 1024
#define G1_KC   16
#define G1_KR   176
#define G1_NCH  (G1_KR / G1_KC)   // 11
#define G1_XSTR 20                // smem row stride (words), 16B-aligned

#define G1_XBUF (G1_ROWS * G1_XSTR)        // floats per x buffer (20480)
#define G1_WBUF (G1_KC * F_HID)            // floats per W buffer (256)
#define G1_SMEM ((2 * G1_XBUF + 2 * G1_WBUF) * 4)  // 165888 B

__global__ void __launch_bounds__(512) k_gemm1(const float* __restrict__ x,
                                               const float* __restrict__ W1) {
    extern __shared__ float smem[];
    const unsigned sbase = (unsigned)__cvta_generic_to_shared(smem);
    const int tid   = threadIdx.x;
    const int row0  = blockIdx.x * G1_ROWS;
    const int kbase = blockIdx.y * G1_KR;
    const int kend  = (kbase + G1_KR < N_NODES) ? kbase + G1_KR : N_NODES;

    // buffer offsets (floats): x0, x1, w0, w1
    const unsigned xoff[2] = { 0u, (unsigned)G1_XBUF };
    const unsigned woff[2] = { (unsigned)(2 * G1_XBUF),
                               (unsigned)(2 * G1_XBUF + G1_WBUF) };

    ull acc[2][8];
#pragma unroll
    for (int r = 0; r < 2; ++r)
#pragma unroll
        for (int j = 0; j < 8; ++j) acc[r][j] = 0ull;

    // ---- async stage of chunk ch into buffer b ----
    auto stage = [&](int ch, int b) {
        const int k0 = kbase + ch * G1_KC;
        // x: 4096 float4s, 8 per thread; lanes -> consecutive (row, c4)
#pragma unroll
        for (int i = 0; i < 8; ++i) {
            int idx  = tid + 512 * i;
            int lrow = idx >> 2, c4 = idx & 3;
            int grow = row0 + lrow; if (grow >= N_NODES) grow = N_NODES - 1;
            int gk   = k0 + c4 * 4;
            int ok   = (gk < kend);
            const float* src = x + (size_t)grow * N_NODES + (ok ? gk : 0);
            unsigned dst = sbase + (xoff[b] + lrow * G1_XSTR + c4 * 4) * 4u;
            cp_async16(dst, src, ok ? 16 : 0);
        }
        // W chunk: 16 rows x 64B = 64 float4s
        if (tid < 64) {
            int k = tid >> 2, c4 = tid & 3;
            int gk = k0 + k;
            int ok = (gk < kend);
            const float* src = W1 + (size_t)(ok ? gk : 0) * F_HID + c4 * 4;
            unsigned dst = sbase + (woff[b] + k * F_HID + c4 * 4) * 4u;
            cp_async16(dst, src, ok ? 16 : 0);
        }
        cp_commit();
    };

    stage(0, 0);

#pragma unroll
    for (int ch = 0; ch < G1_NCH; ++ch) {
        const int b = ch & 1;
        if (ch + 1 < G1_NCH) { stage(ch + 1, b ^ 1); cp_wait<1>(); }
        else                 { cp_wait<0>(); }
        __syncthreads();

        const float* sx = smem + xoff[b];
        const ull*   sw = (const ull*)(smem + woff[b]);

#pragma unroll
        for (int kq = 0; kq < 4; ++kq) {
            float4 xv[2];
#pragma unroll
            for (int rr = 0; rr < 2; ++rr)
                xv[rr] = *(const float4*)&sx[(tid + rr * 512) * G1_XSTR + kq * 4];
#pragma unroll
            for (int e = 0; e < 4; ++e) {
                const int k = kq * 4 + e;
                ulonglong2 w01 = *(const ulonglong2*)&sw[k * 8 + 0];
                ulonglong2 w23 = *(const ulonglong2*)&sw[k * 8 + 2];
                ulonglong2 w45 = *(const ulonglong2*)&sw[k * 8 + 4];
                ulonglong2 w67 = *(const ulonglong2*)&sw[k * 8 + 6];
#pragma unroll
                for (int rr = 0; rr < 2; ++rr) {
                    float xs = (e == 0) ? xv[rr].x : (e == 1) ? xv[rr].y
                             : (e == 2) ? xv[rr].z : xv[rr].w;
                    ull xd = fpack(xs, xs);
                    acc[rr][0] = ffma2(xd, w01.x, acc[rr][0]);
                    acc[rr][1] = ffma2(xd, w01.y, acc[rr][1]);
                    acc[rr][2] = ffma2(xd, w23.x, acc[rr][2]);
                    acc[rr][3] = ffma2(xd, w23.y, acc[rr][3]);
                    acc[rr][4] = ffma2(xd, w45.x, acc[rr][4]);
                    acc[rr][5] = ffma2(xd, w45.y, acc[rr][5]);
                    acc[rr][6] = ffma2(xd, w67.x, acc[rr][6]);
                    acc[rr][7] = ffma2(xd, w67.y, acc[rr][7]);
                }
            }
        }
        __syncthreads();
    }

    // epilogue: each thread owns 2 complete rows -> 4x red.v4 per row
#pragma unroll
    for (int rr = 0; rr < 2; ++rr) {
        int row = row0 + tid + rr * 512;
        if (row < N_NODES) {
            float* o = &g_h1[row * F_HID];
            float2 a0 = funpack(acc[rr][0]), a1 = funpack(acc[rr][1]);
            float2 a2 = funpack(acc[rr][2]), a3 = funpack(acc[rr][3]);
            float2 a4 = funpack(acc[rr][4]), a5 = funpack(acc[rr][5]);
            float2 a6 = funpack(acc[rr][6]), a7 = funpack(acc[rr][7]);
            red_add_v4(o + 0,  a0.x, a0.y, a1.x, a1.y);
            red_add_v4(o + 4,  a2.x, a2.y, a3.x, a3.y);
            red_add_v4(o + 8,  a4.x, a4.y, a5.x, a5.y);
            red_add_v4(o + 12, a6.x, a6.y, a7.x, a7.y);
        }
    }
}

// ---------------- 16-wide propagation (R4 proven versions) ----------------
__global__ void k_self1() {
    int t = blockIdx.x * blockDim.x + threadIdx.x;
    if (t >= N_NODES * 4) return;
    int i = t >> 2;
    float iv = g_inv[i], c = iv * iv;
    float4 v = *(const float4*)&g_h1[t * 4];
    v.x *= c; v.y *= c; v.z *= c; v.w *= c;
    *(float4*)&g_a1[t * 4] = v;
}

template <int L>
__global__ void k_edge_agg(const int* __restrict__ src, const int* __restrict__ dst) {
    int t = blockIdx.x * blockDim.x + threadIdx.x;
    if (t >= E_EDGES * 4) return;
    int e = t >> 2, q = t & 3;
    int s = __ldg(src + e), d = __ldg(dst + e);
    const float* feat  = (L == 1) ? g_h1 : g_hr;
    float*       accum = (L == 1) ? g_a1 : g_p2;
    float c = g_inv[s] * g_inv[d];
    float4 v = *(const float4*)&feat[s * F_HID + q * 4];
    float* a = &accum[d * F_HID + q * 4];
    atomicAdd(a + 0, v.x * c);
    atomicAdd(a + 1, v.y * c);
    atomicAdd(a + 2, v.z * c);
    atomicAdd(a + 3, v.w * c);
}

__global__ void k_relu_self2(const float* __restrict__ b1) {
    int t = blockIdx.x * blockDim.x + threadIdx.x;
    if (t >= N_NODES * 4) return;
    int i = t >> 2, q = t & 3;
    float iv = g_inv[i], c = iv * iv;
    float4 b = *(const float4*)&b1[q * 4];
    float4 h = *(const float4*)&g_a1[t * 4];
    h.x = fmaxf(h.x + b.x, 0.f); h.y = fmaxf(h.y + b.y, 0.f);
    h.z = fmaxf(h.z + b.z, 0.f); h.w = fmaxf(h.w + b.w, 0.f);
    *(float4*)&g_hr[t * 4] = h;
    float4 p = make_float4(h.x * c, h.y * c, h.z * c, h.w * c);
    *(float4*)&g_p2[t * 4] = p;
}

// ---------------- GEMM2 + bias + log_softmax, fused (R4 proven) ----------------
__global__ void __launch_bounds__(256) k_gemm2(const float* __restrict__ W2,
                                               const float* __restrict__ b2,
                                               float* __restrict__ out) {
    extern __shared__ float sZ[];        // [8][N_NODES] = 160000 B
    __shared__ ull sPp[4 * F_HID];       // packed row pairs of p2
    const int tid  = threadIdx.x;
    const int row0 = blockIdx.x * 8;

    if (tid < 4 * F_HID) {
        int pr = tid >> 4, k = tid & 15;
        sPp[tid] = fpack(g_p2[(row0 + 2 * pr) * F_HID + k],
                         g_p2[(row0 + 2 * pr + 1) * F_HID + k]);
    }
    __syncthreads();

    for (int c4 = tid; c4 < N_NODES / 4; c4 += 256) {
        const int c = c4 * 4;
        float4 bv = *(const float4*)&b2[c];
        ull bd0 = fpack(bv.x, bv.x), bd1 = fpack(bv.y, bv.y);
        ull bd2 = fpack(bv.z, bv.z), bd3 = fpack(bv.w, bv.w);
        ull acc[4][4];
#pragma unroll
        for (int pr = 0; pr < 4; ++pr) {
            acc[pr][0] = bd0; acc[pr][1] = bd1; acc[pr][2] = bd2; acc[pr][3] = bd3;
        }
#pragma unroll
        for (int k = 0; k < F_HID; ++k) {
            float4 w = *(const float4*)&W2[k * N_NODES + c];
            ull w0 = fpack(w.x, w.x), w1 = fpack(w.y, w.y);
            ull w2 = fpack(w.z, w.z), w3 = fpack(w.w, w.w);
#pragma unroll
            for (int pr = 0; pr < 4; ++pr) {
                ull pp = sPp[pr * F_HID + k];   // broadcast LDS.64
                acc[pr][0] = ffma2(pp, w0, acc[pr][0]);
                acc[pr][1] = ffma2(pp, w1, acc[pr][1]);
                acc[pr][2] = ffma2(pp, w2, acc[pr][2]);
                acc[pr][3] = ffma2(pp, w3, acc[pr][3]);
            }
        }
#pragma unroll
        for (int pr = 0; pr < 4; ++pr) {
            float2 a0 = funpack(acc[pr][0]), a1 = funpack(acc[pr][1]);
            float2 a2 = funpack(acc[pr][2]), a3 = funpack(acc[pr][3]);
            *(float4*)&sZ[(2 * pr)     * N_NODES + c] = make_float4(a0.x, a1.x, a2.x, a3.x);
            *(float4*)&sZ[(2 * pr + 1) * N_NODES + c] = make_float4(a0.y, a1.y, a2.y, a3.y);
        }
    }
    __syncthreads();

    const int warp = tid >> 5, lane = tid & 31;
    const float4* z4 = (const float4*)(sZ + warp * N_NODES);

    float m = -INFINITY;
    for (int i = lane; i < N_NODES / 4; i += 32) {
        float4 v = z4[i];
        m = fmaxf(m, fmaxf(fmaxf(v.x, v.y), fmaxf(v.z, v.w)));
    }
#pragma unroll
    for (int o = 16; o; o >>= 1) m = fmaxf(m, __shfl_xor_sync(0xffffffffu, m, o));

    float s = 0.0f;
    for (int i = lane; i < N_NODES / 4; i += 32) {
        float4 v = z4[i];
        s += __expf(v.x - m) + __expf(v.y - m) + __expf(v.z - m) + __expf(v.w - m);
    }
#pragma unroll
    for (int o = 16; o; o >>= 1) s += __shfl_xor_sync(0xffffffffu, s, o);

    float lse = m + logf(s);
    float4* orow = (float4*)(out + (size_t)(row0 + warp) * N_NODES);
    for (int i = lane; i < N_NODES / 4; i += 32) {
        float4 v = z4[i];
        orow[i] = make_float4(v.x - lse, v.y - lse, v.z - lse, v.w - lse);
    }
}

// ---------------- launch ----------------
extern "C" void kernel_launch(void* const* d_in, const int* in_sizes, int n_in,
                              void* d_out, int out_size) {
    const float* x   = (const float*)d_in[0];
    const int*   src = (const int*)  d_in[1];
    const int*   dst = (const int*)  d_in[2];
    const float* W1  = (const float*)d_in[3];
    const float* b1  = (const float*)d_in[4];
    const float* W2  = (const float*)d_in[5];
    const float* b2  = (const float*)d_in[6];
    float* out = (float*)d_out;

    const int smem2 = 8 * N_NODES * (int)sizeof(float);  // 160 KB
    cudaFuncSetAttribute(k_gemm2, cudaFuncAttributeMaxDynamicSharedMemorySize, smem2);
    cudaFuncSetAttribute(k_gemm1, cudaFuncAttributeMaxDynamicSharedMemorySize, G1_SMEM);

    k_init     <<<(N_NODES * F_HID + 255) / 256, 256>>>();
    k_deg_edges<<<(E_EDGES + 255) / 256, 256>>>(dst);
    k_rsqrt    <<<(N_NODES + 255) / 256, 256>>>();

    dim3 g1((N_NODES + G1_ROWS - 1) / G1_ROWS,      // 5
            (N_NODES + G1_KR - 1) / G1_KR);         // 29  -> 145 blocks, 1 wave
    k_gemm1<<<g1, 512, G1_SMEM>>>(x, W1);

    k_self1<<<(N_NODES * 4 + 255) / 256, 256>>>();
    k_edge_agg<1><<<(E_EDGES * 4 + 255) / 256, 256>>>(src, dst);

    k_relu_self2<<<(N_NODES * 4 + 255) / 256, 256>>>(b1);
    k_edge_agg<2><<<(E_EDGES * 4 + 255) / 256, 256>>>(src, dst);

    k_gemm2<<<N_NODES / 8, 256, smem2>>>(W2, b2, out);
}